// round 2
// baseline (speedup 1.0000x reference)
#include <cuda_runtime.h>
#include <cstdint>

#define ORD   24
#define TLEN  168
#define DD    512
#define SS    336
#define BB    256
#define ROWF2 26   // float2 slots per coef row: 24 coefs + 1 bias + 1 pad (208B, 16B-aligned)

// Scratch for the coefficient table (no cudaMalloc allowed).
__device__ float2 g_coef[TLEN * ROWF2];

// ---------------------------------------------------------------------------
// Packed fp32x2 helpers (sm_100+/sm_103a). ptxas will NOT auto-fuse these from
// C++ — PTX-only path (SASS_QUICKREF "patterns absent from ptxas output").
// ---------------------------------------------------------------------------
__device__ __forceinline__ unsigned long long fma2(unsigned long long a,
                                                   unsigned long long x,
                                                   unsigned long long c) {
    unsigned long long d;
    asm("fma.rn.f32x2 %0, %1, %2, %3;" : "=l"(d) : "l"(a), "l"(x), "l"(c));
    return d;
}
__device__ __forceinline__ unsigned long long add2(unsigned long long a,
                                                   unsigned long long b) {
    unsigned long long d;
    asm("add.rn.f32x2 %0, %1, %2;" : "=l"(d) : "l"(a), "l"(b));
    return d;
}

// ---------------------------------------------------------------------------
// Kernel A: build coefficient table.
// Thread j (0..24) owns coefficient column j of the sliding window state
// (j==24 is the accumulated-bias column). m[i] = coefficient of ctx_j in
// window slot i. Each step: y_j = sum_i W[i]*m[i] (+b for bias column),
// emit row t, slide window. Pairwise-tree reduction keeps the dependent
// chain short (~30 cyc/step instead of ~100).
// ---------------------------------------------------------------------------
__global__ void ar_coef_kernel(const float* __restrict__ W,
                               const float* __restrict__ b) {
    const int j = threadIdx.x;
    if (j > 24) return;

    float w[ORD];
#pragma unroll
    for (int i = 0; i < ORD; i++) w[i] = W[i];
    const float bias = b[0];

    float m[ORD];
#pragma unroll
    for (int i = 0; i < ORD; i++) m[i] = (j < ORD && i == j) ? 1.0f : 0.0f;

    for (int t = 0; t < TLEN; t++) {
        float p[ORD];
#pragma unroll
        for (int i = 0; i < ORD; i++) p[i] = w[i] * m[i];
#pragma unroll
        for (int k = 0; k < 12; k++) p[k] = p[2 * k] + p[2 * k + 1];
#pragma unroll
        for (int k = 0; k < 6; k++)  p[k] = p[2 * k] + p[2 * k + 1];
#pragma unroll
        for (int k = 0; k < 3; k++)  p[k] = p[2 * k] + p[2 * k + 1];
        float y = (p[0] + p[1]) + p[2];
        if (j == 24) y += bias;

        g_coef[t * ROWF2 + j] = make_float2(y, y);  // duplicated for f32x2

#pragma unroll
        for (int i = 0; i < ORD - 1; i++) m[i] = m[i + 1];
        m[ORD - 1] = y;
    }
}

// ---------------------------------------------------------------------------
// Kernel B: out[b, t, d] = C[t] . ctx[b, :, d] + beta[t]
// One thread per d-quad (float4). ctx (24 x float4) held in registers as
// packed f32x2 pairs. Coef rows broadcast from shared via LDS.128.
// 4 independent accumulator chains for ILP. Coalesced 128B stores.
// ---------------------------------------------------------------------------
__global__ void __launch_bounds__(128)
ar_main_kernel(const float* __restrict__ x, float* __restrict__ out) {
    __shared__ float2 sc[TLEN * ROWF2];

    // Cooperative load of the 34.1 KB coef table (float4 granularity).
    {
        const float4* gsrc = reinterpret_cast<const float4*>(g_coef);
        float4* sdst = reinterpret_cast<float4*>(sc);
        const int n4 = TLEN * ROWF2 / 2;  // 2184
        for (int i = threadIdx.x; i < n4; i += 128) sdst[i] = gsrc[i];
    }
    __syncthreads();

    const int gid   = blockIdx.x * 128 + threadIdx.x;  // 0 .. 32767
    const int batch = gid >> 7;                        // DD/4 = 128 quads/batch
    const int dq    = gid & 127;

    const float* xp = x + ((size_t)batch * SS + (SS - ORD)) * DD + dq * 4;

    unsigned long long cl[ORD], ch[ORD];
#pragma unroll
    for (int jj = 0; jj < ORD; jj++) {
        ulonglong2 v = *reinterpret_cast<const ulonglong2*>(xp + (size_t)jj * DD);
        cl[jj] = v.x;
        ch[jj] = v.y;
    }

    float* op = out + (size_t)batch * TLEN * DD + dq * 4;

    for (int t = 0; t < TLEN; t++) {
        const ulonglong2* row =
            reinterpret_cast<const ulonglong2*>(sc + t * ROWF2);
        const unsigned long long bias =
            *reinterpret_cast<const unsigned long long*>(sc + t * ROWF2 + 24);

        unsigned long long aL0 = bias, aH0 = bias;
        unsigned long long aL1 = 0ull, aH1 = 0ull;
#pragma unroll
        for (int jj = 0; jj < ORD; jj += 2) {
            ulonglong2 c2 = row[jj >> 1];   // coefs jj and jj+1, each {c,c}
            aL0 = fma2(c2.x, cl[jj],     aL0);
            aH0 = fma2(c2.x, ch[jj],     aH0);
            aL1 = fma2(c2.y, cl[jj + 1], aL1);
            aH1 = fma2(c2.y, ch[jj + 1], aH1);
        }
        ulonglong2 r;
        r.x = add2(aL0, aL1);
        r.y = add2(aH0, aH1);
        *reinterpret_cast<ulonglong2*>(op + (size_t)t * DD) = r;
    }
}

// ---------------------------------------------------------------------------
extern "C" void kernel_launch(void* const* d_in, const int* in_sizes, int n_in,
                              void* d_out, int out_size) {
    const float* x = (const float*)d_in[0];   // [256, 336, 512] f32
    const float* W = (const float*)d_in[1];   // [24, 1] f32
    const float* b = (const float*)d_in[2];   // [1] f32
    float* out = (float*)d_out;               // [256, 168, 512] f32

    ar_coef_kernel<<<1, 32>>>(W, b);
    ar_main_kernel<<<(BB * DD / 4) / 128, 128>>>(x, out);
}

// round 3
// speedup vs baseline: 1.1166x; 1.1166x over previous
#include <cuda_runtime.h>
#include <cstdint>

#define ORD   24
#define TLEN  168
#define DD    512
#define SS    336
#define BB    256
#define ROWF2 26          // float2 slots per coef row: 24 coefs + bias + pad (208B)
#define T_CHUNKS 4
#define TCH   (TLEN / T_CHUNKS)      // 42
#define NTILE (BB * T_CHUNKS)        // 1024 tiles (tile = one batch x one T-chunk)
#define GRIDB 592                    // 148 SMs x 4 resident CTAs (128 regs, 35KB smem)

// Scratch (no cudaMalloc allowed).
__device__ float2 g_coef[TLEN * ROWF2];
__device__ int g_counter = 0;   // work-stealing tile counter (self-resets each launch)
__device__ int g_done    = 0;

// ---------------------------------------------------------------------------
// Packed fp32x2 helpers (sm_103a). PTX-only path; ptxas won't auto-fuse.
// ---------------------------------------------------------------------------
__device__ __forceinline__ unsigned long long fma2(unsigned long long a,
                                                   unsigned long long x,
                                                   unsigned long long c) {
    unsigned long long d;
    asm("fma.rn.f32x2 %0, %1, %2, %3;" : "=l"(d) : "l"(a), "l"(x), "l"(c));
    return d;
}
__device__ __forceinline__ unsigned long long add2(unsigned long long a,
                                                   unsigned long long b) {
    unsigned long long d;
    asm("add.rn.f32x2 %0, %1, %2;" : "=l"(d) : "l"(a), "l"(b));
    return d;
}

// ---------------------------------------------------------------------------
// Kernel A: build coefficient table (25 threads; thread j owns the coefficient
// of ctx_j through the 168-step recurrence; j==24 accumulates the bias term).
// ---------------------------------------------------------------------------
__global__ void ar_coef_kernel(const float* __restrict__ W,
                               const float* __restrict__ b) {
    const int j = threadIdx.x;
    if (j > 24) return;

    float w[ORD];
#pragma unroll
    for (int i = 0; i < ORD; i++) w[i] = W[i];
    const float bias = b[0];

    float m[ORD];
#pragma unroll
    for (int i = 0; i < ORD; i++) m[i] = (j < ORD && i == j) ? 1.0f : 0.0f;

    for (int t = 0; t < TLEN; t++) {
        float p[ORD];
#pragma unroll
        for (int i = 0; i < ORD; i++) p[i] = w[i] * m[i];
#pragma unroll
        for (int k = 0; k < 12; k++) p[k] = p[2 * k] + p[2 * k + 1];
#pragma unroll
        for (int k = 0; k < 6; k++)  p[k] = p[2 * k] + p[2 * k + 1];
#pragma unroll
        for (int k = 0; k < 3; k++)  p[k] = p[2 * k] + p[2 * k + 1];
        float y = (p[0] + p[1]) + p[2];
        if (j == 24) y += bias;

        g_coef[t * ROWF2 + j] = make_float2(y, y);  // duplicated for f32x2

#pragma unroll
        for (int i = 0; i < ORD - 1; i++) m[i] = m[i + 1];
        m[ORD - 1] = y;
    }
}

// ---------------------------------------------------------------------------
// Kernel B: persistent work-stealing tiles.
// tile = (chunk, batch); 128 threads = the 128 d-quads of that batch.
// out[b, t, d] = C[t] . ctx[b, :, d] + beta[t] for t in the 42-step chunk.
// ---------------------------------------------------------------------------
__global__ void __launch_bounds__(128, 4)
ar_main_kernel(const float* __restrict__ x, float* __restrict__ out) {
    __shared__ float2 sc[TLEN * ROWF2];   // full 34.1 KB coef table
    __shared__ int s_tile;

    // Cooperative load of the coef table (float4 granularity).
    {
        const float4* gsrc = reinterpret_cast<const float4*>(g_coef);
        float4* sdst = reinterpret_cast<float4*>(sc);
        const int n4 = TLEN * ROWF2 / 2;  // 2184
        for (int i = threadIdx.x; i < n4; i += 128) sdst[i] = gsrc[i];
    }
    const int tid = threadIdx.x;
    __syncthreads();

    for (;;) {
        if (tid == 0) s_tile = atomicAdd(&g_counter, 1);
        __syncthreads();
        const int tile = s_tile;
        if (tile >= NTILE) break;

        const int batch = tile & (BB - 1);   // 0..255
        const int chunk = tile >> 8;         // 0..3
        const int t0 = chunk * TCH;

        // Load ctx: 24 timesteps x float4 for this thread's d-quad.
        const float* xp = x + ((size_t)batch * SS + (SS - ORD)) * DD + tid * 4;
        unsigned long long cl[ORD], ch[ORD];
#pragma unroll
        for (int jj = 0; jj < ORD; jj++) {
            ulonglong2 v = *reinterpret_cast<const ulonglong2*>(xp + (size_t)jj * DD);
            cl[jj] = v.x;
            ch[jj] = v.y;
        }

        float* op = out + (size_t)batch * TLEN * DD + (size_t)t0 * DD + tid * 4;

#pragma unroll 2
        for (int tt = 0; tt < TCH; tt++) {
            const int t = t0 + tt;
            const ulonglong2* row =
                reinterpret_cast<const ulonglong2*>(sc + t * ROWF2);
            const unsigned long long bias =
                *reinterpret_cast<const unsigned long long*>(sc + t * ROWF2 + 24);

            unsigned long long aL0 = bias, aH0 = bias;
            unsigned long long aL1 = 0ull, aH1 = 0ull;
#pragma unroll
            for (int jj = 0; jj < ORD; jj += 2) {
                ulonglong2 c2 = row[jj >> 1];  // coefs jj, jj+1, each {c,c}
                aL0 = fma2(c2.x, cl[jj],     aL0);
                aH0 = fma2(c2.x, ch[jj],     aH0);
                aL1 = fma2(c2.y, cl[jj + 1], aL1);
                aH1 = fma2(c2.y, ch[jj + 1], aH1);
            }
            union { ulonglong2 u; float4 f; } r;
            r.u.x = add2(aL0, aL1);
            r.u.y = add2(aH0, aH1);
            __stcs(reinterpret_cast<float4*>(op + (size_t)tt * DD), r.f);
        }
        __syncthreads();   // protect s_tile before next grab
    }

    // Self-reset counters so every graph replay starts from 0 (deterministic).
    if (tid == 0) {
        const int d = atomicAdd(&g_done, 1);
        if (d == GRIDB - 1) {
            atomicExch(&g_counter, 0);
            atomicExch(&g_done, 0);
        }
    }
}

// ---------------------------------------------------------------------------
extern "C" void kernel_launch(void* const* d_in, const int* in_sizes, int n_in,
                              void* d_out, int out_size) {
    const float* x = (const float*)d_in[0];   // [256, 336, 512] f32
    const float* W = (const float*)d_in[1];   // [24, 1] f32
    const float* b = (const float*)d_in[2];   // [1] f32
    float* out = (float*)d_out;               // [256, 168, 512] f32

    ar_coef_kernel<<<1, 32>>>(W, b);
    ar_main_kernel<<<GRIDB, 128>>>(x, out);
}